// round 3
// baseline (speedup 1.0000x reference)
#include <cuda_runtime.h>
#include <cstdint>

// Problem constants (fixed by reference: B=32, S=2048, D=512)
#define PB   32
#define PS   2048
#define D4   128            // float4 per (b,s) position (512 floats)
#define TILE 16             // positions per block
#define TPB  256            // threads per block
#define TILES_PER_ROW (PS / TILE)   // 128
#define F4_PER_TILE   (TILE * D4)   // 2048 float4
#define F4_PER_THREAD (F4_PER_TILE / TPB) // 8

// ---------------------------------------------------------------------------
// Single fused kernel.
// Block = (row b, tile of 16 consecutive positions).
//  Phase A: cooperative popcount of masks[b, 0:s0)  -> rank base
//  Phase B: warp-scan of the 16 tile mask values    -> per-position rank
//  Phase C: streamed out = seqs + pe[rank] over the tile (8 float4/thread)
// ---------------------------------------------------------------------------
__global__ void __launch_bounds__(TPB, 8)
pe_fused_kernel(const float4* __restrict__ seqs,
                const int*    __restrict__ masks,
                const float4* __restrict__ pe,
                float4*       __restrict__ out)
{
    const int blk  = blockIdx.x;
    const int b    = blk >> 7;            // / TILES_PER_ROW
    const int tile = blk & (TILES_PER_ROW - 1);
    const int s0   = tile * TILE;

    const int* m = masks + b * PS;

    const int t    = threadIdx.x;
    const int lane = t & 31;
    const int w    = t >> 5;

    // ---- Phase A: popcount of masks[b, 0:s0) ----
    int cnt = 0;
    for (int i = t; i < s0; i += TPB)
        cnt += (m[i] != 0);

    #pragma unroll
    for (int off = 16; off; off >>= 1)
        cnt += __shfl_down_sync(0xFFFFFFFFu, cnt, off);

    __shared__ int red[TPB / 32];
    if (lane == 0) red[w] = cnt;
    __syncthreads();

    // ---- Phase B: warp 0 computes per-position rank for the tile ----
    __shared__ int rank_s[TILE];
    if (w == 0) {
        int base = (lane < TPB / 32) ? red[lane] : 0;
        #pragma unroll
        for (int off = 4; off; off >>= 1)
            base += __shfl_down_sync(0xFFFFFFFFu, base, off);
        base = __shfl_sync(0xFFFFFFFFu, base, 0);

        // inclusive scan over the 16 tile positions (lanes 0..15 used)
        const int mv = (lane < TILE) ? ((m[s0 + lane] != 0) ? 1 : 0) : 0;
        int incl = mv;
        #pragma unroll
        for (int off = 1; off < TILE; off <<= 1) {
            int v = __shfl_up_sync(0xFFFFFFFFu, incl, off);
            if (lane >= off) incl += v;
        }
        if (lane < TILE)
            rank_s[lane] = mv ? (base + incl - 1) : -1;
    }
    __syncthreads();

    // ---- Phase C: stream the tile ----
    const size_t cbase = ((size_t)(b * PS + s0)) * D4;

    #pragma unroll
    for (int k = 0; k < F4_PER_THREAD; k++) {
        const int off = t + k * TPB;          // 0 .. 2047
        const int sl  = off >> 7;             // local position 0..15
        const int col = off & (D4 - 1);
        const int r   = rank_s[sl];

        float4 v = __ldcs(seqs + cbase + off);
        if (r >= 0) {
            const float4 p = __ldg(pe + (size_t)r * D4 + col);
            v.x += p.x; v.y += p.y; v.z += p.z; v.w += p.w;
        }
        __stcs(out + cbase + off, v);
    }
}

// ---------------------------------------------------------------------------
// Launch.
// Inputs (metadata order): seqs [B,S,D] f32, masks [B,S] int32, pe [2048,D] f32
// Output: [B,S,D] f32
// ---------------------------------------------------------------------------
extern "C" void kernel_launch(void* const* d_in, const int* in_sizes, int n_in,
                              void* d_out, int out_size)
{
    const float* seqs  = (const float*)d_in[0];
    const int*   masks = (const int*)d_in[1];
    const float* pe    = (const float*)d_in[2];
    float*       out   = (float*)d_out;

    (void)in_sizes; (void)n_in; (void)out_size;

    const int blocks = PB * TILES_PER_ROW;   // 32 * 128 = 4096
    pe_fused_kernel<<<blocks, TPB>>>(
        (const float4*)seqs, masks, (const float4*)pe, (float4*)out);
}

// round 4
// speedup vs baseline: 1.0447x; 1.0447x over previous
#include <cuda_runtime.h>
#include <cstdint>

// Problem constants (fixed by reference: B=32, S=2048, D=512)
#define PB 32
#define PS 2048
#define D4 128              // float4 per (b,s) position

// Scratch: rank per (b,s). rank >= 0 iff mask set; -1 otherwise.
__device__ int g_rank[PB * PS];

// ---------------------------------------------------------------------------
// Kernel 1: per-row inclusive scan of the mask (int32) -> ranks.
// One block (1024 threads) per row; each thread handles 2 consecutive ints.
// ---------------------------------------------------------------------------
__global__ void __launch_bounds__(1024, 1)
rank_scan_kernel(const int* __restrict__ masks)
{
    const int b = blockIdx.x;
    const int* m = masks + (size_t)b * PS;
    const int t = threadIdx.x;
    const int lane = t & 31;
    const int warp = t >> 5;

    const int i0 = 2 * t;
    const int2 mv = *reinterpret_cast<const int2*>(m + i0);
    const int m0 = (mv.x != 0) ? 1 : 0;
    const int m1 = (mv.y != 0) ? 1 : 0;
    const int s = m0 + m1;

    int incl = s;
    #pragma unroll
    for (int off = 1; off < 32; off <<= 1) {
        int v = __shfl_up_sync(0xFFFFFFFFu, incl, off);
        if (lane >= off) incl += v;
    }

    __shared__ int warp_tot[32];
    if (lane == 31) warp_tot[warp] = incl;
    __syncthreads();

    if (warp == 0) {
        int v = warp_tot[lane];
        int wincl = v;
        #pragma unroll
        for (int off = 1; off < 32; off <<= 1) {
            int u = __shfl_up_sync(0xFFFFFFFFu, wincl, off);
            if (lane >= off) wincl += u;
        }
        warp_tot[lane] = wincl - v;   // exclusive warp base
    }
    __syncthreads();

    const int base = warp_tot[warp];
    const int excl_thread = base + (incl - s);

    const int c0 = excl_thread + m0;
    const int c1 = c0 + m1;

    int2 rv;
    rv.x = m0 ? (c0 - 1) : -1;
    rv.y = m1 ? (c1 - 1) : -1;
    *reinterpret_cast<int2*>(g_rank + (size_t)b * PS + i0) = rv;
}

// ---------------------------------------------------------------------------
// Kernel 2: out = seqs + (rank >= 0 ? pe[rank] : 0).
// 2 float4 per thread, front-batched loads for MLP; streaming hints keep
// seqs/out out of L2 so pe (4 MiB) stays resident.
// ---------------------------------------------------------------------------
__global__ void __launch_bounds__(256, 8)
pe_add_kernel(const float4* __restrict__ seqs,
              const float4* __restrict__ pe,
              float4*       __restrict__ out)
{
    const unsigned t    = threadIdx.x;
    const unsigned idx0 = blockIdx.x * 512u + t;       // element 0
    const unsigned idx1 = idx0 + 256u;                 // element 1

    const unsigned row0 = idx0 >> 7;
    const unsigned row1 = idx1 >> 7;
    const unsigned col0 = idx0 & 127u;
    const unsigned col1 = idx1 & 127u;

    // Front-batch all independent loads
    const int r0 = __ldg(&g_rank[row0]);
    const int r1 = __ldg(&g_rank[row1]);
    float4 v0 = __ldcs(seqs + idx0);
    float4 v1 = __ldcs(seqs + idx1);

    if (r0 >= 0) {
        const float4 p = __ldg(pe + (unsigned)r0 * D4 + col0);
        v0.x += p.x; v0.y += p.y; v0.z += p.z; v0.w += p.w;
    }
    if (r1 >= 0) {
        const float4 p = __ldg(pe + (unsigned)r1 * D4 + col1);
        v1.x += p.x; v1.y += p.y; v1.z += p.z; v1.w += p.w;
    }

    __stcs(out + idx0, v0);
    __stcs(out + idx1, v1);
}

// ---------------------------------------------------------------------------
// Launch.
// Inputs (metadata order): seqs [B,S,D] f32, masks [B,S] int32, pe [2048,D] f32
// Output: [B,S,D] f32
// ---------------------------------------------------------------------------
extern "C" void kernel_launch(void* const* d_in, const int* in_sizes, int n_in,
                              void* d_out, int out_size)
{
    const float* seqs  = (const float*)d_in[0];
    const int*   masks = (const int*)d_in[1];
    const float* pe    = (const float*)d_in[2];
    float*       out   = (float*)d_out;

    (void)in_sizes; (void)n_in; (void)out_size;

    rank_scan_kernel<<<PB, 1024>>>(masks);

    const unsigned total4 = (unsigned)PB * PS * D4;    // 8,388,608
    pe_add_kernel<<<total4 / 512, 256>>>(
        (const float4*)seqs, (const float4*)pe, (float4*)out);
}